// round 1
// baseline (speedup 1.0000x reference)
#include <cuda_runtime.h>
#include <cstdint>

// Problem constants (fixed shapes)
#define BATCH   32
#define NA      9
#define FH      64
#define FW      64
#define HW      (FH*FW)          // 4096
#define NPROP   (HW*NA)          // 36864
#define TOPK    300
#define SD4     64               // SAMPLE_DURATION*4
#define OUTC    66               // 1 + 64 + 1

// Anchor (w,h) table; centers are always (8+16*gx, 8+16*gy)
__constant__ float c_aw[9] = {92.f,184.f,368.f,64.f,128.f,256.f,44.f,88.f,176.f};
__constant__ float c_ah[9] = {48.f,96.f,192.f,64.f,128.f,256.f,88.f,176.f,352.f};

// Selected proposal indices per (batch, rank)
__device__ int g_sel[BATCH * TOPK];

// Dynamic smem layout
#define SM_KEYS_BYTES   (NPROP * 4)          // 147456
#define SM_SEL_OFF      SM_KEYS_BYTES
#define SM_SEL_BYTES    (512 * 8)            // 4096
#define SM_HIST_OFF     (SM_SEL_OFF + SM_SEL_BYTES)
#define SM_HIST_BYTES   (256 * 4)
#define SM_TOTAL        (SM_HIST_OFF + SM_HIST_BYTES)   // 152576

__global__ __launch_bounds__(1024, 1)
void topk_kernel(const float* __restrict__ scores_in, float* __restrict__ out)
{
    extern __shared__ unsigned char smem_raw[];
    unsigned* keys = (unsigned*)smem_raw;
    unsigned long long* sel = (unsigned long long*)(smem_raw + SM_SEL_OFF);
    unsigned* hist = (unsigned*)(smem_raw + SM_HIST_OFF);
    __shared__ unsigned long long s_pref;
    __shared__ int s_rem;
    __shared__ int s_cnt;

    const int b = blockIdx.x;
    const int tid = threadIdx.x;
    const unsigned lane = tid & 31u;

    // Load scores (fg half of channels), build monotonic uint32 keys.
    // score n = (hw*9 + a) <- scores_in[b, 9+a, hw]
    const float* sp = scores_in + (size_t)b * 18 * HW + (size_t)NA * HW;
    #pragma unroll
    for (int a = 0; a < 9; a++) {
        for (int i = tid; i < HW; i += 1024) {
            float s = sp[a * HW + i];
            unsigned u = __float_as_uint(s);
            unsigned k = (u & 0x80000000u) ? ~u : (u | 0x80000000u);
            keys[i * 9 + a] = k;   // stride-9 words: gcd(9,32)=1 -> conflict free
        }
    }
    if (tid == 0) { s_rem = TOPK; s_pref = 0ull; s_cnt = 0; }
    __syncthreads();

    // 8-pass byte radix-select for the exact 300th-largest 64-bit key.
    // key64 = (key32 << 32) | ~idx  (unique; ties -> lower idx wins, matches jax top_k)
    for (int p = 7; p >= 0; p--) {
        for (int d = tid; d < 256; d += 1024) hist[d] = 0;
        __syncthreads();
        const unsigned long long pref = s_pref;
        const unsigned long long maskhi =
            (p == 7) ? 0ull : ~((1ull << (8 * (p + 1))) - 1ull);
        for (int n = tid; n < NPROP; n += 1024) {
            unsigned long long k64 =
                ((unsigned long long)keys[n] << 32) | (unsigned)(~n);
            int ok = ((k64 & maskhi) == pref);
            unsigned bin = (unsigned)(k64 >> (8 * p)) & 0xFFu;
            unsigned m = __ballot_sync(0xFFFFFFFFu, ok);
            if (ok) {
                // warp-aggregated histogram (kills same-bin atomic serialization)
                unsigned mm = __match_any_sync(m, bin);
                if (lane == (unsigned)(__ffs(mm) - 1))
                    atomicAdd(&hist[bin], __popc(mm));
            }
        }
        __syncthreads();
        if (tid == 0) {
            int rem = s_rem;
            unsigned cum = 0;
            int d = 255;
            for (; d >= 0; d--) {
                unsigned c = hist[d];
                if (cum + c >= (unsigned)rem) break;
                cum += c;
            }
            s_rem = rem - (int)cum;
            s_pref = pref | ((unsigned long long)(unsigned)d << (8 * p));
        }
        __syncthreads();
    }
    const unsigned long long T = s_pref;   // exact 300th-largest key (unique keys)

    // Compact: exactly 300 keys >= T
    for (int n = tid; n < NPROP; n += 1024) {
        unsigned long long k64 =
            ((unsigned long long)keys[n] << 32) | (unsigned)(~n);
        if (k64 >= T) {
            int pos = atomicAdd(&s_cnt, 1);
            sel[pos] = k64;
        }
    }
    for (int i = tid; i < 512; i += 1024)
        if (i >= TOPK) sel[i] = 0ull;      // disjoint from compaction writes
    __syncthreads();

    // Bitonic sort 512 keys descending
    for (int k = 2; k <= 512; k <<= 1) {
        for (int j = k >> 1; j > 0; j >>= 1) {
            if (tid < 512) {
                int i = tid, ixj = i ^ j;
                if (ixj > i) {
                    unsigned long long a = sel[i], c = sel[ixj];
                    bool up = ((i & k) == 0);
                    if (up ? (a < c) : (a > c)) { sel[i] = c; sel[ixj] = a; }
                }
            }
            __syncthreads();
        }
    }

    // Emit ranks: batch col, score col, and selected indices for decode kernel
    for (int i = tid; i < TOPK; i += 1024) {
        unsigned long long k64 = sel[i];
        unsigned k32 = (unsigned)(k64 >> 32);
        int n = (int)(~(unsigned)k64);
        unsigned u = (k32 & 0x80000000u) ? (k32 & 0x7FFFFFFFu) : ~k32;
        float sc = __uint_as_float(u);
        g_sel[b * TOPK + i] = n;
        size_t row = ((size_t)b * TOPK + i) * OUTC;
        out[row + 0] = (float)b;
        out[row + OUTC - 1] = sc;
    }
}

// One block per (rank, batch); 64 threads, one output coordinate each.
__global__ __launch_bounds__(64)
void decode_kernel(const float* __restrict__ bbox,
                   const float* __restrict__ im_info,
                   float* __restrict__ out)
{
    const int i = blockIdx.x;       // rank 0..299
    const int b = blockIdx.y;       // batch
    const int k = threadIdx.x;      // 0..63 = t*4 + j

    const int n  = g_sel[b * TOPK + i];
    const int a  = n % 9;
    const int hw = n / 9;
    const float w  = c_aw[a];
    const float h  = c_ah[a];
    const float cx = 8.0f + 16.0f * (float)(hw & 63);
    const float cy = 8.0f + 16.0f * (float)(hw >> 6);

    // delta[k] = bbox[b, a*64 + k, hw]
    const float d = bbox[((size_t)b * (NA * SD4) + (size_t)a * SD4 + k) * HW + hw];

    const unsigned base = (threadIdx.x & 31u) & ~3u;
    const float d0 = __shfl_sync(0xFFFFFFFFu, d, base + 0);
    const float d1 = __shfl_sync(0xFFFFFFFFu, d, base + 1);
    const float d2 = __shfl_sync(0xFFFFFFFFu, d, base + 2);
    const float d3 = __shfl_sync(0xFFFFFFFFu, d, base + 3);

    const float xmax = im_info[b * 3 + 1] - 1.0f;
    const float ymax = im_info[b * 3 + 0] - 1.0f;

    const float pcx = d0 * w + cx;
    const float pcy = d1 * h + cy;
    const float pw  = expf(d2) * w;
    const float ph  = expf(d3) * h;

    float v;
    switch (k & 3) {
        case 0: v = fminf(fmaxf(pcx - 0.5f * pw, 0.0f), xmax); break;
        case 1: v = fminf(fmaxf(pcy - 0.5f * ph, 0.0f), ymax); break;
        case 2: v = fminf(fmaxf(pcx + 0.5f * pw, 0.0f), xmax); break;
        default: v = fminf(fmaxf(pcy + 0.5f * ph, 0.0f), ymax); break;
    }

    out[((size_t)b * TOPK + i) * OUTC + 1 + k] = v;
}

extern "C" void kernel_launch(void* const* d_in, const int* in_sizes, int n_in,
                              void* d_out, int out_size)
{
    const float* scores  = (const float*)d_in[0];  // (32,18,64,64)
    const float* bbox    = (const float*)d_in[1];  // (32,576,64,64)
    const float* im_info = (const float*)d_in[2];  // (32,3)
    float* out = (float*)d_out;                    // (32,300,66)

    cudaFuncSetAttribute(topk_kernel,
                         cudaFuncAttributeMaxDynamicSharedMemorySize, SM_TOTAL);

    topk_kernel<<<BATCH, 1024, SM_TOTAL>>>(scores, out);
    decode_kernel<<<dim3(TOPK, BATCH), 64>>>(bbox, im_info, out);
}

// round 2
// speedup vs baseline: 1.8787x; 1.8787x over previous
#include <cuda_runtime.h>
#include <cstdint>

#define BATCH   32
#define NA      9
#define FH      64
#define FW      64
#define HW      (FH*FW)          // 4096
#define NPROP   (HW*NA)          // 36864
#define NVEC    (NPROP/4)        // 9216 float4 per batch
#define TOPK    300
#define OUTC    66               // 1 + 64 + 1
#define CAND_CAP 2048

// Anchor (w,h) table; centers are always (8+16*gx, 8+16*gy)
__constant__ float c_aw[9] = {92.f,184.f,368.f,64.f,128.f,256.f,44.f,88.f,176.f};
__constant__ float c_ah[9] = {48.f,96.f,192.f,64.f,128.f,256.f,88.f,176.f,352.f};

__device__ int       g_sel[BATCH * TOPK];
__device__ unsigned  g_thresh[BATCH];
__device__ int       g_cnt[BATCH];
__device__ unsigned long long g_cand[BATCH * CAND_CAP];

__device__ __forceinline__ unsigned f2key(float s) {
    unsigned u = __float_as_uint(s);
    return (u & 0x80000000u) ? ~u : (u | 0x80000000u);
}

// ---------------------------------------------------------------------------
// Stage 1: per-batch 4096-bin histogram of top-12 key bits + suffix scan to
// find the bin containing rank-300. One CTA per batch.
// ---------------------------------------------------------------------------
__global__ __launch_bounds__(1024, 1)
void hist_kernel(const float* __restrict__ scores_in)
{
    __shared__ unsigned hist[4096];
    __shared__ unsigned wsum[32];
    __shared__ unsigned wpre[32];

    const int b = blockIdx.x;
    const int tid = threadIdx.x;
    const unsigned lane = tid & 31u;
    const int warp = tid >> 5;

    #pragma unroll
    for (int i = tid; i < 4096; i += 1024) hist[i] = 0;
    if (tid == 0) g_cnt[b] = 0;
    __syncthreads();

    // fg scores: scores_in[b, 9.., :] -> 36864 contiguous floats
    const float4* sp = (const float4*)(scores_in + (size_t)b * 18 * HW + (size_t)NA * HW);
    #pragma unroll 3
    for (int i = tid; i < NVEC; i += 1024) {
        float4 v = sp[i];
        atomicAdd(&hist[f2key(v.x) >> 20], 1u);
        atomicAdd(&hist[f2key(v.y) >> 20], 1u);
        atomicAdd(&hist[f2key(v.z) >> 20], 1u);
        atomicAdd(&hist[f2key(v.w) >> 20], 1u);
    }
    __syncthreads();

    // suffix scan from the top: thread t owns bins [4095-4t .. 4092-4t]
    const int bhi = 4095 - 4 * tid;
    unsigned h0 = hist[bhi],     h1 = hist[bhi - 1];
    unsigned h2 = hist[bhi - 2], h3 = hist[bhi - 3];
    unsigned s = h0 + h1 + h2 + h3;
    unsigned incl = s;
    #pragma unroll
    for (int o = 1; o < 32; o <<= 1) {
        unsigned v = __shfl_up_sync(0xFFFFFFFFu, incl, o);
        if (lane >= o) incl += v;
    }
    if (lane == 31) wsum[warp] = incl;
    __syncthreads();
    if (warp == 0) {
        unsigned w = wsum[lane];
        unsigned wi = w;
        #pragma unroll
        for (int o = 1; o < 32; o <<= 1) {
            unsigned v = __shfl_up_sync(0xFFFFFFFFu, wi, o);
            if (lane >= o) wi += v;
        }
        wpre[lane] = wi - w;     // exclusive prefix of warp totals
    }
    __syncthreads();

    unsigned c = wpre[warp] + (incl - s);   // count in bins strictly above bhi
    unsigned hh[4] = {h0, h1, h2, h3};
    #pragma unroll
    for (int j = 0; j < 4; j++) {
        if (c < TOPK && c + hh[j] >= TOPK)
            g_thresh[b] = ((unsigned)(bhi - j)) << 20;
        c += hh[j];
    }
}

// ---------------------------------------------------------------------------
// Stage 2: compact candidates (key >= threshold). 4 CTAs per batch.
// ---------------------------------------------------------------------------
__global__ __launch_bounds__(1024)
void compact_kernel(const float* __restrict__ scores_in)
{
    const int b = blockIdx.y;
    const int tid = threadIdx.x;
    const unsigned thr = g_thresh[b];

    const float4* sp = (const float4*)(scores_in + (size_t)b * 18 * HW + (size_t)NA * HW);
    for (int i = blockIdx.x * 1024 + tid; i < NVEC; i += 4 * 1024) {
        float4 v = sp[i];
        const int idx0 = 4 * i;                  // memory index: a*4096 + hw
        float vv[4] = {v.x, v.y, v.z, v.w};
        #pragma unroll
        for (int j = 0; j < 4; j++) {
            unsigned k = f2key(vv[j]);
            if (k >= thr) {
                int idx = idx0 + j;
                int a = idx >> 12, hw = idx & 4095;
                int n = hw * 9 + a;              // jax flat index
                int pos = atomicAdd(&g_cnt[b], 1);
                if (pos < CAND_CAP)
                    g_cand[b * CAND_CAP + pos] =
                        ((unsigned long long)k << 32) | (unsigned)(~n);
            }
        }
    }
}

// ---------------------------------------------------------------------------
// Stage 3: bitonic sort candidates, emit top-300. One CTA per batch.
// ---------------------------------------------------------------------------
__global__ __launch_bounds__(1024, 1)
void sort_kernel(float* __restrict__ out)
{
    __shared__ unsigned long long sel[CAND_CAP];
    const int b = blockIdx.x;
    const int tid = threadIdx.x;
    const int cnt = min(g_cnt[b], CAND_CAP);

    for (int i = tid; i < CAND_CAP; i += 1024)
        sel[i] = (i < cnt) ? g_cand[b * CAND_CAP + i] : 0ull;
    __syncthreads();

    for (int k = 2; k <= CAND_CAP; k <<= 1) {
        for (int j = k >> 1; j > 0; j >>= 1) {
            for (int i = tid; i < CAND_CAP; i += 1024) {
                int ixj = i ^ j;
                if (ixj > i) {
                    unsigned long long a = sel[i], c = sel[ixj];
                    bool up = ((i & k) == 0);
                    if (up ? (a < c) : (a > c)) { sel[i] = c; sel[ixj] = a; }
                }
            }
            __syncthreads();
        }
    }

    for (int i = tid; i < TOPK; i += 1024) {
        unsigned long long k64 = sel[i];
        unsigned k32 = (unsigned)(k64 >> 32);
        int n = (int)(~(unsigned)k64);
        unsigned u = (k32 & 0x80000000u) ? (k32 & 0x7FFFFFFFu) : ~k32;
        g_sel[b * TOPK + i] = n;
        size_t row = ((size_t)b * TOPK + i) * OUTC;
        out[row + 0] = (float)b;
        out[row + OUTC - 1] = __uint_as_float(u);
    }
}

// ---------------------------------------------------------------------------
// Decode: 4 ranks per 256-thread block; one thread per output coordinate.
// ---------------------------------------------------------------------------
__global__ __launch_bounds__(256)
void decode_kernel(const float* __restrict__ bbox,
                   const float* __restrict__ im_info,
                   float* __restrict__ out)
{
    const int tid = threadIdx.x;
    const int i = blockIdx.x * 4 + (tid >> 6);  // rank 0..299
    const int b = blockIdx.y;
    const int k = tid & 63;

    const int n  = g_sel[b * TOPK + i];
    const int a  = n % 9;
    const int hw = n / 9;
    const float w  = c_aw[a];
    const float h  = c_ah[a];
    const float cx = 8.0f + 16.0f * (float)(hw & 63);
    const float cy = 8.0f + 16.0f * (float)(hw >> 6);

    const float d = bbox[((size_t)b * (NA * 64) + (size_t)a * 64 + k) * HW + hw];

    const unsigned base = (tid & 31u) & ~3u;
    const float d0 = __shfl_sync(0xFFFFFFFFu, d, base + 0);
    const float d1 = __shfl_sync(0xFFFFFFFFu, d, base + 1);
    const float d2 = __shfl_sync(0xFFFFFFFFu, d, base + 2);
    const float d3 = __shfl_sync(0xFFFFFFFFu, d, base + 3);

    const float xmax = im_info[b * 3 + 1] - 1.0f;
    const float ymax = im_info[b * 3 + 0] - 1.0f;

    const float pcx = d0 * w + cx;
    const float pcy = d1 * h + cy;
    const float pw  = expf(d2) * w;
    const float ph  = expf(d3) * h;

    float v;
    switch (k & 3) {
        case 0: v = fminf(fmaxf(pcx - 0.5f * pw, 0.0f), xmax); break;
        case 1: v = fminf(fmaxf(pcy - 0.5f * ph, 0.0f), ymax); break;
        case 2: v = fminf(fmaxf(pcx + 0.5f * pw, 0.0f), xmax); break;
        default: v = fminf(fmaxf(pcy + 0.5f * ph, 0.0f), ymax); break;
    }

    out[((size_t)b * TOPK + i) * OUTC + 1 + k] = v;
}

extern "C" void kernel_launch(void* const* d_in, const int* in_sizes, int n_in,
                              void* d_out, int out_size)
{
    const float* scores  = (const float*)d_in[0];  // (32,18,64,64)
    const float* bbox    = (const float*)d_in[1];  // (32,576,64,64)
    const float* im_info = (const float*)d_in[2];  // (32,3)
    float* out = (float*)d_out;                    // (32,300,66)

    hist_kernel<<<BATCH, 1024>>>(scores);
    compact_kernel<<<dim3(4, BATCH), 1024>>>(scores);
    sort_kernel<<<BATCH, 1024>>>(out);
    decode_kernel<<<dim3(TOPK / 4, BATCH), 256>>>(bbox, im_info, out);
}

// round 3
// speedup vs baseline: 3.1708x; 1.6877x over previous
#include <cuda_runtime.h>
#include <cstdint>

#define BATCH   32
#define NA      9
#define HW      4096
#define NPROP   (HW*NA)          // 36864
#define NVEC    (NPROP/4)        // 9216 float4 per batch
#define TOPK    300
#define OUTC    66
#define CAP     2048

// Anchor (w,h) table; centers are always (8+16*gx, 8+16*gy)
__constant__ float c_aw[9] = {92.f,184.f,368.f,64.f,128.f,256.f,44.f,88.f,176.f};
__constant__ float c_ah[9] = {48.f,96.f,192.f,64.f,128.f,256.f,88.f,176.f,352.f};

// decode feed: per batch, ascending-n order; packed = n | (rank<<16)
__device__ unsigned g_dec[BATCH * TOPK];

__device__ __forceinline__ unsigned f2key(float s) {
    unsigned u = __float_as_uint(s);
    return (u & 0x80000000u) ? ~u : (u | 0x80000000u);
}

// ---------------------------------------------------------------------------
// Fused exact top-k: hist -> threshold -> compact(smem) -> rank-by-count.
// One CTA per batch.
// ---------------------------------------------------------------------------
__global__ __launch_bounds__(1024, 1)
void topk_fused(const float* __restrict__ scores_in, float* __restrict__ out)
{
    __shared__ unsigned hist[4096];
    __shared__ unsigned long long cand[CAP];
    __shared__ unsigned sel_n[TOPK];
    __shared__ unsigned wsum[32], wpre[32];
    __shared__ unsigned s_thr;
    __shared__ int s_cnt;

    const int b = blockIdx.x;
    const int tid = threadIdx.x;
    const unsigned lane = tid & 31u;
    const int warp = tid >> 5;

    #pragma unroll
    for (int i = tid; i < 4096; i += 1024) hist[i] = 0;
    if (tid == 0) s_cnt = 0;
    __syncthreads();

    // Pass 1: histogram of top-12 key bits (DRAM read, 147KB/batch)
    const float4* sp = (const float4*)(scores_in + (size_t)b * 18 * HW + (size_t)NA * HW);
    #pragma unroll 3
    for (int i = tid; i < NVEC; i += 1024) {
        float4 v = sp[i];
        atomicAdd(&hist[f2key(v.x) >> 20], 1u);
        atomicAdd(&hist[f2key(v.y) >> 20], 1u);
        atomicAdd(&hist[f2key(v.z) >> 20], 1u);
        atomicAdd(&hist[f2key(v.w) >> 20], 1u);
    }
    __syncthreads();

    // Parallel suffix-scan from the top: thread t owns bins [4095-4t .. 4092-4t]
    const int bhi = 4095 - 4 * tid;
    unsigned h0 = hist[bhi],     h1 = hist[bhi - 1];
    unsigned h2 = hist[bhi - 2], h3 = hist[bhi - 3];
    unsigned s = h0 + h1 + h2 + h3;
    unsigned incl = s;
    #pragma unroll
    for (int o = 1; o < 32; o <<= 1) {
        unsigned v = __shfl_up_sync(0xFFFFFFFFu, incl, o);
        if (lane >= o) incl += v;
    }
    if (lane == 31) wsum[warp] = incl;
    __syncthreads();
    if (warp == 0) {
        unsigned w = wsum[lane];
        unsigned wi = w;
        #pragma unroll
        for (int o = 1; o < 32; o <<= 1) {
            unsigned v = __shfl_up_sync(0xFFFFFFFFu, wi, o);
            if (lane >= o) wi += v;
        }
        wpre[lane] = wi - w;
    }
    __syncthreads();
    {
        unsigned c = wpre[warp] + (incl - s);  // count strictly above bin bhi
        unsigned hh[4] = {h0, h1, h2, h3};
        #pragma unroll
        for (int j = 0; j < 4; j++) {
            if (c < TOPK && c + hh[j] >= TOPK)
                s_thr = ((unsigned)(bhi - j)) << 20;
            c += hh[j];
        }
    }
    __syncthreads();
    const unsigned thr = s_thr;

    // Pass 2: compact candidates (L2-resident re-read)
    #pragma unroll 3
    for (int i = tid; i < NVEC; i += 1024) {
        float4 v = sp[i];
        float vv[4] = {v.x, v.y, v.z, v.w};
        #pragma unroll
        for (int j = 0; j < 4; j++) {
            unsigned k = f2key(vv[j]);
            if (k >= thr) {
                int idx = 4 * i + j;             // memory order: a*4096 + hw
                int a = idx >> 12, hw = idx & 4095;
                int n = hw * 9 + a;              // jax flat order
                int pos = atomicAdd(&s_cnt, 1);
                if (pos < CAP)
                    cand[pos] = ((unsigned long long)k << 32) | (unsigned)(~n);
            }
        }
    }
    __syncthreads();
    const int C = min(s_cnt, CAP);

    // Exact rank by counting (keys unique -> matches jax top_k tie-break)
    for (int i = tid; i < C; i += 1024) {
        const unsigned long long me = cand[i];
        int r = 0;
        for (int j = 0; j < C; j++) r += (cand[j] > me);   // smem broadcast
        if (r < TOPK) {
            unsigned n = (unsigned)(~(unsigned)me) & 0xFFFFu;
            sel_n[r] = n;
            unsigned k32 = (unsigned)(me >> 32);
            unsigned u = (k32 & 0x80000000u) ? (k32 & 0x7FFFFFFFu) : ~k32;
            size_t row = ((size_t)b * TOPK + r) * OUTC;
            out[row + 0] = (float)b;
            out[row + OUTC - 1] = __uint_as_float(u);
        }
    }
    __syncthreads();

    // Decode order: ascending flat index n (better DRAM/L2 locality)
    if (tid < TOPK) {
        unsigned n = sel_n[tid];
        int o = 0;
        for (int j = 0; j < TOPK; j++) o += (sel_n[j] < n);
        g_dec[b * TOPK + o] = n | ((unsigned)tid << 16);
    }
}

// ---------------------------------------------------------------------------
// Decode: 8 proposals per 512-thread block, in ascending-address order.
// ---------------------------------------------------------------------------
__global__ __launch_bounds__(512)
void decode_kernel(const float* __restrict__ bbox,
                   const float* __restrict__ im_info,
                   float* __restrict__ out)
{
    const int tid = threadIdx.x;
    const int j = blockIdx.x * 8 + (tid >> 6);
    const int b = blockIdx.y;
    const int k = tid & 63;
    if (j >= TOPK) return;                     // 64-thread groups: warp-uniform

    const unsigned packed = g_dec[b * TOPK + j];
    const int n    = packed & 0xFFFFu;
    const int rank = packed >> 16;

    const int a  = n % 9;
    const int hw = n / 9;
    const float w  = c_aw[a];
    const float h  = c_ah[a];
    const float cx = 8.0f + 16.0f * (float)(hw & 63);
    const float cy = 8.0f + 16.0f * (float)(hw >> 6);

    const float d = __ldcs(&bbox[((size_t)b * (NA * 64) + (size_t)a * 64 + k) * HW + hw]);

    const unsigned base = (tid & 31u) & ~3u;
    const float d0 = __shfl_sync(0xFFFFFFFFu, d, base + 0);
    const float d1 = __shfl_sync(0xFFFFFFFFu, d, base + 1);
    const float d2 = __shfl_sync(0xFFFFFFFFu, d, base + 2);
    const float d3 = __shfl_sync(0xFFFFFFFFu, d, base + 3);

    const float xmax = im_info[b * 3 + 1] - 1.0f;
    const float ymax = im_info[b * 3 + 0] - 1.0f;

    const float pcx = d0 * w + cx;
    const float pcy = d1 * h + cy;
    const float pw  = expf(d2) * w;
    const float ph  = expf(d3) * h;

    float v;
    switch (k & 3) {
        case 0: v = fminf(fmaxf(pcx - 0.5f * pw, 0.0f), xmax); break;
        case 1: v = fminf(fmaxf(pcy - 0.5f * ph, 0.0f), ymax); break;
        case 2: v = fminf(fmaxf(pcx + 0.5f * pw, 0.0f), xmax); break;
        default: v = fminf(fmaxf(pcy + 0.5f * ph, 0.0f), ymax); break;
    }

    out[((size_t)b * TOPK + rank) * OUTC + 1 + k] = v;
}

extern "C" void kernel_launch(void* const* d_in, const int* in_sizes, int n_in,
                              void* d_out, int out_size)
{
    const float* scores  = (const float*)d_in[0];  // (32,18,64,64)
    const float* bbox    = (const float*)d_in[1];  // (32,576,64,64)
    const float* im_info = (const float*)d_in[2];  // (32,3)
    float* out = (float*)d_out;                    // (32,300,66)

    topk_fused<<<BATCH, 1024>>>(scores, out);
    decode_kernel<<<dim3((TOPK + 7) / 8, BATCH), 512>>>(bbox, im_info, out);
}